// round 8
// baseline (speedup 1.0000x reference)
#include <cuda_runtime.h>
#include <cuda_bf16.h>
#include <math.h>
#include <stdint.h>

// ---------------- problem constants ----------------
#define B_      128
#define STREAM_ 512
#define INCH    4
#define EXTRA_  5
#define G_      2
#define STEP_   16
#define SIGC    1110        // C + C^2 + C^3, C=10
#define W_      31          // windows
#define F_      2220        // GROUPS * SIGC
#define RNN_    256
#define OUT_    10
#define KP2     2240        // F_ padded to multiple of 64 (bf16 chunk)
#define MROWS   (W_ * B_)   // 3968
#define NGI     768         // 3 * RNN
#define NC      (KP2 / 64)  // 35 K-chunks of 64 bf16 (128 bytes)

// ---------------- device scratch (static, allowed) ----------------
__device__ __nv_bfloat16 g_A0[MROWS * KP2];   // sig hi  (~17.8 MB)
__device__ __nv_bfloat16 g_A1[MROWS * KP2];   // sig lo
__device__ __nv_bfloat16 g_B0[NGI * KP2];     // W_ih hi (~3.4 MB)
__device__ __nv_bfloat16 g_B1[NGI * KP2];     // W_ih lo
__device__ float g_gi[MROWS * NGI];           // ~12 MB
__device__ float g_h [2][B_ * RNN_];          // ping-pong hidden state

// grid barrier state (self-resetting; gen monotonic across graph replays)
__device__ volatile unsigned g_bar_gen;
__device__ unsigned g_bar_cnt;

// ---------------- PTX helpers (portable: sm_80/90 class only) ----------------
__device__ __forceinline__ uint32_t smem_u32(const void* p) {
    uint32_t a;
    asm("{ .reg .u64 t; cvta.to.shared.u64 t, %1; cvt.u32.u64 %0, t; }" : "=r"(a) : "l"(p));
    return a;
}

__device__ __forceinline__ uint32_t swz(uint32_t off) { return off ^ ((off >> 3) & 0x70); }

#define LDSM4(r0, r1, r2, r3, addr)                                               \
    asm volatile("ldmatrix.sync.aligned.m8n8.x4.shared.b16 {%0,%1,%2,%3}, [%4];"  \
        : "=r"(r0), "=r"(r1), "=r"(r2), "=r"(r3) : "r"(addr))

// D += A(16x16) * B(16x8), bf16 in, fp32 accum. row.col = both K-contiguous.
#define MMA16816(d, a, b0v, b1v)                                                  \
    asm volatile("mma.sync.aligned.m16n8k16.row.col.f32.bf16.bf16.f32 "           \
        "{%0,%1,%2,%3}, {%4,%5,%6,%7}, {%8,%9}, {%0,%1,%2,%3};"                   \
        : "+f"((d)[0]), "+f"((d)[1]), "+f"((d)[2]), "+f"((d)[3])                  \
        : "r"((a)[0]), "r"((a)[1]), "r"((a)[2]), "r"((a)[3]), "r"(b0v), "r"(b1v))

// split fp32 -> two bf16 (hi = rn(v), lo = rn(v - hi))
__device__ __forceinline__ void store_split(size_t idx, float v,
                                            __nv_bfloat16* a0, __nv_bfloat16* a1) {
    __nv_bfloat16 h = __float2bfloat16(v);
    a0[idx] = h;
    a1[idx] = __float2bfloat16(v - __bfloat162float(h));
}

// =====================================================================
// Kernel 1: path signatures (Chen, depth 3) -> split bf16 into g_A0/g_A1
// =====================================================================
__global__ __launch_bounds__(128) void sig_kernel(
    const float* __restrict__ x,       // (128,512,4)
    const float* __restrict__ W_aug)   // (2,5,4)
{
    const int w  = blockIdx.x;
    const int bg = blockIdx.y;
    const int b  = bg >> 1;
    const int g  = bg & 1;
    const int tid = threadIdx.x;

    __shared__ __align__(16) float xs[32][4];
    __shared__ __align__(16) float dxw[31][10];

    {
        int row = tid >> 2, ch = tid & 3;
        xs[row][ch] = x[(b * STREAM_ + w * STEP_ + row) * INCH + ch];
    }
    __syncthreads();

    for (int idx = tid; idx < 31 * 10; idx += 128) {
        int j = idx / 10, c = idx % 10;
        float v;
        if (c < 4) {
            v = xs[j + 1][c] - xs[j][c];
        } else if (c == 4) {
            v = 1.0f / 511.0f;
        } else {
            int e = c - 5;
            const float* wa = W_aug + (g * EXTRA_ + e) * INCH;
            v = 0.f;
            #pragma unroll
            for (int i = 0; i < 4; i++) v += wa[i] * (xs[j + 1][i] - xs[j][i]);
        }
        dxw[j][c] = v;
    }
    __syncthreads();

    const size_t base = (size_t)(w * B_ + b) * KP2 + (size_t)g * SIGC;

    if (tid < 100) {
        const int a  = tid / 10;
        const int bb = tid % 10;
        float s1a = 0.f, s2 = 0.f;
        float s3[10];
        #pragma unroll
        for (int c = 0; c < 10; c++) s3[c] = 0.f;

        for (int j = 0; j < 31; j++) {
            float dxa = dxw[j][a];
            float dxb = dxw[j][bb];
            float factor = s2 + dxb * (0.5f * s1a + (1.0f / 6.0f) * dxa);
            #pragma unroll
            for (int c = 0; c < 10; c++) s3[c] += factor * dxw[j][c];
            s2  += dxb * (s1a + 0.5f * dxa);
            s1a += dxa;
        }
        if (bb == 0) store_split(base + a, s1a, g_A0, g_A1);
        store_split(base + 10 + tid, s2, g_A0, g_A1);
        #pragma unroll
        for (int c = 0; c < 10; c++)
            store_split(base + 110 + tid * 10 + c, s3[c], g_A0, g_A1);
    }
    // zero K-pad columns (g==1 block handles it once per row)
    if (g == 1 && tid < (KP2 - F_)) {
        size_t idx = (size_t)(w * B_ + b) * KP2 + F_ + tid;
        g_A0[idx] = __float2bfloat16(0.f);
        g_A1[idx] = __float2bfloat16(0.f);
    }
}

// =====================================================================
// Kernel 2: split+pad W_ih (768 x 2220) into g_B0/g_B1 (768 x 2240)
// =====================================================================
__global__ __launch_bounds__(256) void prep_w(const float* __restrict__ Wih)
{
    int idx = blockIdx.x * 256 + threadIdx.x;
    if (idx < NGI * KP2) {
        int n = idx / KP2, k = idx - n * KP2;
        float v = (k < F_) ? Wih[n * F_ + k] : 0.f;
        store_split((size_t)idx, v, g_B0, g_B1);
    }
}

// =====================================================================
// Kernel 3: GI = sig @ W_ih^T + b_ih via mma.sync bf16-split (3 products).
// 64x128 CTA tile (372 tiles, 2 CTAs/SM), 8 warps of 32(M)x32(N),
// K-chunk 64, double-buffered cp.async, SW128 smem, ldmatrix TN.
// =====================================================================
#define A_TILE_B    8192                   // 64 rows x 128 bytes
#define B_TILE_B    16384                  // 128 rows x 128 bytes
#define STAGE_B     (2 * A_TILE_B + 2 * B_TILE_B)   // 49152
#define GEMM_SMEM   (2 * STAGE_B)          // 98304 bytes (2 stages)

__global__ __launch_bounds__(256, 2) void gemm_mma(const float* __restrict__ bih)
{
    extern __shared__ char smem[];
    const uint32_t sb = smem_u32(smem);
    const int tid  = threadIdx.x;
    const int lane = tid & 31;
    const int wid  = tid >> 5;
    const int wm   = wid & 1;         // M offset 32*wm
    const int wn   = wid >> 1;        // 0..3 -> N offset 32*wn
    const int m0 = blockIdx.x * 64;
    const int n0 = blockIdx.y * 128;

    const __nv_bfloat16* aA0 = g_A0 + (size_t)m0 * KP2;
    const __nv_bfloat16* aA1 = g_A1 + (size_t)m0 * KP2;
    const __nv_bfloat16* bB0g = g_B0 + (size_t)n0 * KP2;
    const __nv_bfloat16* bB1g = g_B1 + (size_t)n0 * KP2;

    auto load_chunk = [&](int c) {
        uint32_t sbase = sb + (uint32_t)(c & 1) * STAGE_B;
        #pragma unroll
        for (int tt = 0; tt < 2; tt++) {
            const __nv_bfloat16* gp = tt ? aA1 : aA0;
            #pragma unroll
            for (int it = 0; it < 2; it++) {
                int i = tid + it * 256;           // 0..511
                int row = i >> 3, seg = i & 7;
                uint32_t dst = sbase + (uint32_t)tt * A_TILE_B
                             + swz((uint32_t)row * 128 + (uint32_t)seg * 16);
                const void* src = gp + (size_t)row * KP2 + (size_t)c * 64 + seg * 8;
                asm volatile("cp.async.cg.shared.global [%0], [%1], 16;\n"
                             :: "r"(dst), "l"(src));
            }
        }
        #pragma unroll
        for (int tt = 0; tt < 2; tt++) {
            const __nv_bfloat16* gp = tt ? bB1g : bB0g;
            #pragma unroll
            for (int it = 0; it < 4; it++) {
                int i = tid + it * 256;           // 0..1023
                int row = i >> 3, seg = i & 7;
                uint32_t dst = sbase + 2 * A_TILE_B + (uint32_t)tt * B_TILE_B
                             + swz((uint32_t)row * 128 + (uint32_t)seg * 16);
                const void* src = gp + (size_t)row * KP2 + (size_t)c * 64 + seg * 8;
                asm volatile("cp.async.cg.shared.global [%0], [%1], 16;\n"
                             :: "r"(dst), "l"(src));
            }
        }
        asm volatile("cp.async.commit_group;\n" ::: "memory");
    };

    float acc[2][4][4];
    #pragma unroll
    for (int i = 0; i < 2; i++)
        #pragma unroll
        for (int jj = 0; jj < 4; jj++)
            #pragma unroll
            for (int k = 0; k < 4; k++) acc[i][jj][k] = 0.f;

    const uint32_t a_row  = (uint32_t)(wm * 32 + (lane & 15));
    const uint32_t a_byte = (uint32_t)((lane >> 4) << 4);
    const uint32_t b_row  = (uint32_t)(wn * 32 + (lane & 7) + ((lane >> 4) << 3));
    const uint32_t b_byte = (uint32_t)((lane & 8) << 1);

    load_chunk(0);

    for (int c = 0; c < NC; c++) {
        if (c + 1 < NC) load_chunk(c + 1);
        if (c + 1 < NC) asm volatile("cp.async.wait_group 1;\n" ::: "memory");
        else            asm volatile("cp.async.wait_group 0;\n" ::: "memory");
        __syncthreads();

        const uint32_t stage = sb + (uint32_t)(c & 1) * STAGE_B;
        const uint32_t aB0 = stage;
        const uint32_t aB1 = stage + A_TILE_B;
        const uint32_t bB0 = stage + 2 * A_TILE_B;
        const uint32_t bB1 = stage + 2 * A_TILE_B + B_TILE_B;

        #pragma unroll
        for (int ks = 0; ks < 4; ks++) {
            const uint32_t kb = (uint32_t)ks * 32;
            uint32_t a0f[2][4], a1f[2][4];
            #pragma unroll
            for (int mt = 0; mt < 2; mt++) {
                uint32_t off = swz((a_row + mt * 16) * 128 + kb + a_byte);
                LDSM4(a0f[mt][0], a0f[mt][1], a0f[mt][2], a0f[mt][3], aB0 + off);
                LDSM4(a1f[mt][0], a1f[mt][1], a1f[mt][2], a1f[mt][3], aB1 + off);
            }
            uint32_t b0f[2][4], b1f[2][4];
            #pragma unroll
            for (int nt = 0; nt < 2; nt++) {
                uint32_t off = swz((b_row + nt * 16) * 128 + kb + b_byte);
                LDSM4(b0f[nt][0], b0f[nt][1], b0f[nt][2], b0f[nt][3], bB0 + off);
                LDSM4(b1f[nt][0], b1f[nt][1], b1f[nt][2], b1f[nt][3], bB1 + off);
            }
            #pragma unroll
            for (int mt = 0; mt < 2; mt++) {
                #pragma unroll
                for (int nt = 0; nt < 2; nt++) {
                    MMA16816(acc[mt][2 * nt],     a0f[mt], b0f[nt][0], b0f[nt][1]);
                    MMA16816(acc[mt][2 * nt + 1], a0f[mt], b0f[nt][2], b0f[nt][3]);
                    MMA16816(acc[mt][2 * nt],     a0f[mt], b1f[nt][0], b1f[nt][1]);
                    MMA16816(acc[mt][2 * nt + 1], a0f[mt], b1f[nt][2], b1f[nt][3]);
                    MMA16816(acc[mt][2 * nt],     a1f[mt], b0f[nt][0], b0f[nt][1]);
                    MMA16816(acc[mt][2 * nt + 1], a1f[mt], b0f[nt][2], b0f[nt][3]);
                }
            }
        }
        __syncthreads();
    }

    float2 bias[4];
    {
        const int nbase = n0 + wn * 32 + 2 * (lane & 3);
        #pragma unroll
        for (int nt8 = 0; nt8 < 4; nt8++) {
            bias[nt8].x = bih[nbase + nt8 * 8];
            bias[nt8].y = bih[nbase + nt8 * 8 + 1];
        }
    }
    #pragma unroll
    for (int mt = 0; mt < 2; mt++) {
        const int mlo = m0 + wm * 32 + mt * 16 + (lane >> 2);
        #pragma unroll
        for (int nt8 = 0; nt8 < 4; nt8++) {
            const int n = n0 + wn * 32 + nt8 * 8 + 2 * (lane & 3);
            float2 lo, hi;
            lo.x = acc[mt][nt8][0] + bias[nt8].x;
            lo.y = acc[mt][nt8][1] + bias[nt8].y;
            hi.x = acc[mt][nt8][2] + bias[nt8].x;
            hi.y = acc[mt][nt8][3] + bias[nt8].y;
            *(float2*)(g_gi + (size_t)mlo * NGI + n)       = lo;
            *(float2*)(g_gi + (size_t)(mlo + 8) * NGI + n) = hi;
        }
    }
}

// =====================================================================
// Kernel 4: persistent GRU v3 (512 threads, W_hh in registers) + head.
// 128 CTAs = 8 b-tiles(16) x 16 j-tiles(16), 512 threads (16 warps).
// Warp w owns gate column j = j0 + w. Lane kc (0..31) owns k-slice
// kc*8..+7: W_hh[3][8] in 24 registers for all 31 steps.
// Per step: conflict-free LDS of h (layout [b][i2][kc][4]), 384 FMA,
// then 4 halving butterfly rounds over kc&15 + final xor-16 (48 SHFL),
// landing (b = b0 + (lane&15), j) sums on lanes 0..15 (dup on 16..31).
// =====================================================================
#define GRU_CTAS   128

__global__ __launch_bounds__(512, 1) void gru_persist(
    const float* __restrict__ Whh,   // (768,256)
    const float* __restrict__ bhh,   // (768)
    const float* __restrict__ Wout,  // (10,256)
    const float* __restrict__ bout,  // (10)
    float* __restrict__ out)         // (128,10)
{
    // hs[b][i2][kc][4] : element k of row b at ((b*2 + (k>>2)&1)*32 + (k>>3))*4 + (k&3)
    __shared__ __align__(16) float hs[4096];   // 16 KB

    const int tid  = threadIdx.x;
    const int w    = tid >> 5;           // 0..15
    const int lane = tid & 31;
    const int kc   = lane;               // k-slice owner (0..31)
    const int kl   = lane & 15;          // butterfly b-index
    const int bt = blockIdx.x >> 4, jt = blockIdx.x & 15;
    const int b0 = bt * 16, j0 = jt * 16;
    const int j  = j0 + w;               // this warp's gate column
    const int b  = b0 + kl;              // this lane's output batch row

    // ---- one-time: W_hh[3 gates][my 8-k slice] -> registers ----
    float4 W4[3][2];
    #pragma unroll
    for (int g = 0; g < 3; g++)
        #pragma unroll
        for (int i2 = 0; i2 < 2; i2++)
            W4[g][i2] = *(const float4*)&Whh[(g * RNN_ + j) * RNN_ + kc * 8 + i2 * 4];

    const float br = bhh[j], bz = bhh[RNN_ + j], bn = bhh[2 * RNN_ + j];
    // h_prev smem index for (b row, col j):  kc_s=j>>3, i2=(j>>2)&1, e=j&3
    const int hprev_idx = ((b - b0) * 2 + ((j >> 2) & 1)) * 128 + (j >> 3) * 4 + (j & 3);

    for (int t = 0; t < W_; t++) {
        // ---- fill hs (swizzled) : 1024 float4, 2 per thread ----
        if (t == 0) {
            #pragma unroll
            for (int i = tid; i < 1024; i += 512)
                *(float4*)&hs[i * 4] = make_float4(0.f, 0.f, 0.f, 0.f);
        } else {
            const float* hi = g_h[t & 1];
            #pragma unroll
            for (int i = tid; i < 1024; i += 512) {
                int bb = i >> 6, q = i & 63;         // q = k/4
                int kcs = q >> 1, i2 = q & 1;
                float4 v = __ldcg((const float4*)&hi[(b0 + bb) * RNN_ + q * 4]);
                *(float4*)&hs[((bb * 2 + i2) * 32 + kcs) * 4] = v;
            }
        }
        __syncthreads();

        // prefetch gi for this lane's output (consumed after reduction)
        const float* gi_t = g_gi + (size_t)t * (B_ * NGI) + (size_t)b * NGI;
        float ir  = __ldcg(&gi_t[j]);
        float iz  = __ldcg(&gi_t[RNN_ + j]);
        float inn = __ldcg(&gi_t[2 * RNN_ + j]);

        // ---- partials: all 16 b-rows over my 8-k slice (384 FMA) ----
        float acc[16][3];
        #pragma unroll
        for (int bb = 0; bb < 16; bb++) {
            float4 h0 = *(const float4*)&hs[((bb * 2 + 0) * 32 + kc) * 4];
            float4 h1 = *(const float4*)&hs[((bb * 2 + 1) * 32 + kc) * 4];
            #pragma unroll
            for (int g = 0; g < 3; g++) {
                float s;
                s  = W4[g][0].x * h0.x + W4[g][0].y * h0.y + W4[g][0].z * h0.z + W4[g][0].w * h0.w;
                s += W4[g][1].x * h1.x + W4[g][1].y * h1.y + W4[g][1].z * h1.z + W4[g][1].w * h1.w;
                acc[bb][g] = s;
            }
        }

        // ---- butterfly reduce: 4 halving rounds over kc&15, then xor-16 ----
        #pragma unroll
        for (int m = 8; m >= 1; m >>= 1) {
            #pragma unroll
            for (int bb = 0; bb < m; bb++) {
                #pragma unroll
                for (int g = 0; g < 3; g++) {
                    float lo = acc[bb][g], hi2 = acc[bb + m][g];
                    float send = (kl & m) ? lo  : hi2;
                    float keep = (kl & m) ? hi2 : lo;
                    acc[bb][g] = keep + __shfl_xor_sync(0xffffffffu, send, m);
                }
            }
        }
        #pragma unroll
        for (int g = 0; g < 3; g++)
            acc[0][g] += __shfl_xor_sync(0xffffffffu, acc[0][g], 16);

        // ---- gates for (b, j); lanes 0..15 write (16..31 duplicates) ----
        float r = 1.f / (1.f + expf(-(ir + acc[0][0] + br)));
        float z = 1.f / (1.f + expf(-(iz + acc[0][1] + bz)));
        float n = tanhf(inn + r * (acc[0][2] + bn));
        float hprev = hs[hprev_idx];
        if (lane < 16)
            g_h[(t + 1) & 1][b * RNN_ + j] = (1.f - z) * n + z * hprev;

        // ---- grid barrier ----
        __threadfence();
        __syncthreads();
        if (tid == 0) {
            unsigned gen = g_bar_gen;
            if (atomicAdd(&g_bar_cnt, 1u) == GRU_CTAS - 1) {
                g_bar_cnt = 0;
                __threadfence();
                g_bar_gen = gen + 1;
            } else {
                while (g_bar_gen == gen) __nanosleep(32);
            }
        }
        __syncthreads();
    }

    // ---- output head: 8 CTAs (jt==0), 16 b-rows x 10 outputs each ----
    if (jt == 0) {
        const float* hf = g_h[W_ & 1];   // g_h[1]
        for (int i = tid; i < 16 * OUT_; i += 512) {
            int bb = b0 + i / OUT_, o = i % OUT_;
            float s = 0.f;
            #pragma unroll 8
            for (int k = 0; k < RNN_; k += 4) {
                float4 h4 = __ldcg((const float4*)&hf[bb * RNN_ + k]);
                float4 w4 = *(const float4*)&Wout[o * RNN_ + k];
                s += h4.x * w4.x + h4.y * w4.y + h4.z * w4.z + h4.w * w4.w;
            }
            out[bb * OUT_ + o] = 1.f / (1.f + expf(-(s + bout[o])));
        }
    }
}

// =====================================================================
extern "C" void kernel_launch(void* const* d_in, const int* in_sizes, int n_in,
                              void* d_out, int out_size)
{
    const float* x     = (const float*)d_in[0];
    const float* W_aug = (const float*)d_in[1];
    // d_in[2] = b_aug: constant, cancels in increments
    const float* W_ih  = (const float*)d_in[3];
    const float* W_hh  = (const float*)d_in[4];
    const float* b_ih  = (const float*)d_in[5];
    const float* b_hh  = (const float*)d_in[6];
    const float* W_out = (const float*)d_in[7];
    const float* b_out = (const float*)d_in[8];
    float* out = (float*)d_out;

    cudaFuncSetAttribute(gemm_mma, cudaFuncAttributeMaxDynamicSharedMemorySize, GEMM_SMEM);

    sig_kernel<<<dim3(W_, B_ * G_), 128>>>(x, W_aug);
    prep_w<<<(NGI * KP2 + 255) / 256, 256>>>(W_ih);
    gemm_mma<<<dim3(MROWS / 64, NGI / 128), 256, GEMM_SMEM>>>(b_ih);
    gru_persist<<<GRU_CTAS, 512>>>(W_hh, b_hh, W_out, b_out, out);
}